// round 10
// baseline (speedup 1.0000x reference)
#include <cuda_runtime.h>
#include <math.h>

// ---------------- problem constants ----------------
constexpr int CB   = 256;   // batch
constexpr int CTXD = 512;
constexpr int DOF  = 6;
constexpr int WSZ  = 300;
constexpr int PGD  = 256;
constexpr int PWD  = 512;
constexpr int HGD  = 256;
constexpr int HWD  = 512;
constexpr int ZD   = 306;   // DOF + WSZ
constexpr int NSTEP = 19;   // max_segments - 1
constexpr int NW   = PWD * ZD;   // 156672 = big-GEMM N

// ---------------- scratch layout (single __device__ array, no allocs) ----------
constexpr size_t OFF_TMPW = 0;
constexpr size_t SZ_TMPW  = (size_t)CB * NW;                 // 40,108,032
constexpr size_t OFF_BWT  = OFF_TMPW + SZ_TMPW;              // [o*306+j][i]
constexpr size_t SZ_BWT   = (size_t)NW * CTXD;               // 80,216,064
constexpr size_t OFF_TMPG = OFF_BWT + SZ_BWT;
constexpr size_t SZ_TMPG  = (size_t)CB * PGD * DOF;
constexpr size_t OFF_CTXT = OFF_TMPG + SZ_TMPG;
constexpr size_t OFF_PG   = OFF_CTXT + (size_t)CTXD * CB;
constexpr size_t OFF_PW   = OFF_PG + (size_t)CB * DOF;
constexpr size_t OFF_XPRE = OFF_PW + (size_t)CB * WSZ;
constexpr size_t OFF_YPRE = OFF_XPRE + (size_t)CB * PGD;
constexpr size_t OFF_X    = OFF_YPRE + (size_t)CB * PWD;
constexpr size_t OFF_Y    = OFF_X + (size_t)CB * PGD;
// zero-init region (states used as step-1 inputs)
constexpr size_t OFF_ZERO = OFF_Y + (size_t)CB * PWD;
constexpr size_t OFF_GH0A = OFF_ZERO;
constexpr size_t OFF_GH1A = OFF_GH0A + (size_t)CB * HGD;
constexpr size_t OFF_WH0A = OFF_GH1A + (size_t)CB * HGD;
constexpr size_t OFF_WH1A = OFF_WH0A + (size_t)CB * HWD;
constexpr size_t OFF_GC0  = OFF_WH1A + (size_t)CB * HWD;
constexpr size_t OFF_GC1  = OFF_GC0 + (size_t)CB * HGD;
constexpr size_t OFF_WC0  = OFF_GC1 + (size_t)CB * HGD;
constexpr size_t OFF_WC1  = OFF_WC0 + (size_t)CB * HWD;
constexpr size_t SZ_ZERO  = OFF_WC1 + (size_t)CB * HWD - OFF_ZERO;
// double-buffer "B" halves (not zeroed)
constexpr size_t OFF_GH0B = OFF_WC1 + (size_t)CB * HWD;
constexpr size_t OFF_GH1B = OFF_GH0B + (size_t)CB * HGD;
constexpr size_t OFF_WH0B = OFF_GH1B + (size_t)CB * HGD;
constexpr size_t OFF_WH1B = OFF_WH0B + (size_t)CB * HWD;
constexpr size_t SZ_TOTAL = OFF_WH1B + (size_t)CB * HWD;

__device__ float g_buf[SZ_TOTAL];

__device__ __forceinline__ float sigm(float x) { return 1.0f / (1.0f + expf(-x)); }

__device__ __forceinline__ float f2tf(float f) {
    unsigned u;
    asm("cvt.rna.tf32.f32 %0, %1;" : "=r"(u) : "f"(f));
    return __uint_as_float(u);
}

// ---------------- transpose ctx -> ctxT[i][b] (for k_tmpg coalescing) ---------
__global__ void k_transpose_ctx(const float* __restrict__ ctx) {
    int idx = blockIdx.x * 256 + threadIdx.x;
    if (idx >= CB * CTXD) return;
    int b = idx / CTXD, i = idx % CTXD;
    g_buf[OFF_CTXT + (size_t)i * CB + b] = ctx[idx];
}

// ---------------- transpose bw_W[o][i][j] -> bwT[(o*306+j)][i] ----------------
__global__ void k_transb(const float* __restrict__ bwW) {
    __shared__ float t[32][33];
    int o = blockIdx.z;
    int j0 = blockIdx.x * 32, i0 = blockIdx.y * 32;
    int tx = threadIdx.x, ty = threadIdx.y;   // 32 x 8
#pragma unroll
    for (int r = 0; r < 32; r += 8) {
        int i = i0 + ty + r, j = j0 + tx;
        float v = (j < ZD) ? bwW[((size_t)o * CTXD + i) * ZD + j] : 0.f;
        t[ty + r][tx] = v;
    }
    __syncthreads();
#pragma unroll
    for (int r = 0; r < 32; r += 8) {
        int j = j0 + ty + r, i = i0 + tx;
        if (j < ZD)
            g_buf[OFF_BWT + ((size_t)o * ZD + j) * CTXD + i] = t[tx][ty + r];
    }
}

// ---------------- tmp_g[b][o][j] = sum_i ctx[b,i] * bg_W[o,i,j] ----------------
__global__ __launch_bounds__(256) void k_tmpg(const float* __restrict__ bgW) {
    int o = blockIdx.x;
    int b = threadIdx.x;
    float acc[DOF];
#pragma unroll
    for (int j = 0; j < DOF; ++j) acc[j] = 0.f;
    const float* ctxT = &g_buf[OFF_CTXT];
    for (int i = 0; i < CTXD; ++i) {
        float c = ctxT[(size_t)i * CB + b];
        const float* w = &bgW[((size_t)o * CTXD + i) * DOF];
#pragma unroll
        for (int j = 0; j < DOF; ++j) acc[j] = fmaf(c, w[j], acc[j]);
    }
    float* out = &g_buf[OFF_TMPG + ((size_t)b * PGD + o) * DOF];
#pragma unroll
    for (int j = 0; j < DOF; ++j) out[j] = acc[j];
}

// ---------------- init: zero states, seed outputs and pg/pw -------------------
__global__ void k_init(const float* __restrict__ goal0, const float* __restrict__ w0,
                       float* __restrict__ out) {
    int idx = blockIdx.x * 256 + threadIdx.x;
    const int R0 = (int)SZ_ZERO;
    const int R2 = CB * DOF;
    const int R3 = CB * WSZ;
    if (idx < R0) {
        g_buf[OFF_ZERO + idx] = 0.f;
    } else if (idx < R0 + R2) {
        int j = idx - R0;
        float v = goal0[j];
        g_buf[OFF_PG + j] = v;
        out[(size_t)(j / DOF) * 20 * DOF + (j % DOF)] = v;   // goals[:,0,:]
    } else if (idx < R0 + R2 + R3) {
        int j = idx - R0 - R2;
        float v = w0[j];
        g_buf[OFF_PW + j] = v;
        out[(size_t)CB * 20 * DOF + (size_t)(j / WSZ) * 20 * WSZ + (j % WSZ)] = v;
    }
}

// ---------------- per-step bilinear: ypre (tmp_w matvec) + xpre ---------------
__global__ __launch_bounds__(256) void k_bilinear(const float* __restrict__ bg_b,
                                                  const float* __restrict__ bw_b) {
    int b = blockIdx.x;
    int tile = blockIdx.y;
    __shared__ float zs[ZD];
    int tid = threadIdx.x;
    for (int j = tid; j < ZD; j += 256)
        zs[j] = (j < DOF) ? g_buf[OFF_PG + b * DOF + j]
                          : g_buf[OFF_PW + b * WSZ + (j - DOF)];
    __syncthreads();

    if (tile == 8) {
        int o = tid;
        const float* tg = &g_buf[OFF_TMPG + ((size_t)b * PGD + o) * DOF];
        float acc = bg_b[o];
#pragma unroll
        for (int j = 0; j < DOF; ++j) acc = fmaf(tg[j], zs[j], acc);
        g_buf[OFF_XPRE + b * PGD + o] = acc;
        return;
    }
    int w = tid >> 5, lane = tid & 31;
#pragma unroll
    for (int r = 0; r < 8; ++r) {
        int o = tile * 64 + w * 8 + r;
        const float* tw = &g_buf[OFF_TMPW + (size_t)b * NW + (size_t)o * ZD];
        float acc = 0.f;
        for (int j = lane; j < ZD; j += 32) acc = fmaf(tw[j], zs[j], acc);
#pragma unroll
        for (int s = 16; s > 0; s >>= 1) acc += __shfl_xor_sync(0xffffffffu, acc, s);
        if (lane == 0) g_buf[OFF_YPRE + b * PWD + o] = acc + bw_b[o];
    }
}

// ================= 3xTF32 mma.sync GEMM-NT ===================================
// C[M,N] = ep( A1 @ B1^T + A2 @ B2^T + biases ),  A row-major [M,K], B [N,K]
// Split precision: x = hi + lo (hi = tf32(x), lo = tf32(x-hi));
// acc += hi_A*hi_B + hi_A*lo_B + lo_A*hi_B  -> ~fp32 accuracy on tensor cores.
// BM=128, BN=64, BK=16; 256 threads = 8 warps (4m x 2n), warp tile 32x32.
// mode 0: plain (+bias, optional dual-dest), mode 1: +tanh, mode 2: LSTM fused.

struct Prob {
    const float *A1, *B1; int K1;
    const float *A2, *B2; int K2;     // A2 == nullptr -> single phase
    const float *bias1, *bias2;       // nullable
    float *C;  int ldc;
    float *C2; int ldc2;              // nullable second destination
    int M, N;
    int mode;                         // 0 plain, 1 tanh, 2 lstm
    int H;                            // lstm hidden size
    float *c_st;                      // lstm cell state [b][H] (in/out)
    float *h_out;                     // lstm h output [b][H]
};

#define BM 128
#define BN 64
#define BK 16
#define SSTR (BK + 4)                 // 20

__global__ __launch_bounds__(256) void k_mma(Prob p0, Prob p1) {
    Prob p = blockIdx.z ? p1 : p0;
    int bx = blockIdx.x;
    int n_tiles = (p.mode == 2) ? (p.H / 16) : ((p.N + BN - 1) / BN);
    if (bx >= n_tiles) return;
    int m0 = blockIdx.y * BM;

    __shared__ float smem[8192];                 // 32KB; tiles | reused for gates
    float* sAh = smem;                           // [BM][SSTR] = 2560
    float* sAl = smem + BM * SSTR;               // 2560
    float* sBh = smem + 2 * BM * SSTR;           // [BN][SSTR] = 1280
    float* sBl = smem + 2 * BM * SSTR + BN * SSTR;

    int tid  = threadIdx.x;
    int lane = tid & 31;
    int warp = tid >> 5;
    int wm = warp & 3;                           // 4 m-warps * 32
    int wn = warp >> 2;                          // 2 n-warps * 32

    float acc[2][4][4];
#pragma unroll
    for (int a = 0; a < 2; ++a)
#pragma unroll
        for (int b = 0; b < 4; ++b)
#pragma unroll
            for (int c = 0; c < 4; ++c) acc[a][b][c] = 0.f;

    int lr = tid >> 2;                           // 0..63
    int lc = (tid & 3) * 4;                      // 0,4,8,12

#pragma unroll 1
    for (int ph = 0; ph < 2; ++ph) {
        const float* A = ph ? p.A2 : p.A1;
        const float* B = ph ? p.B2 : p.B1;
        int K = ph ? p.K2 : p.K1;
        if (A == nullptr) continue;
#pragma unroll 1
        for (int k0 = 0; k0 < K; k0 += BK) {
            __syncthreads();
            // load A tile: BM x BK, split hi/lo
#pragma unroll
            for (int i = 0; i < 2; ++i) {
                int row = lr + i * 64;
                float4 v = *(const float4*)&A[(size_t)(m0 + row) * K + k0 + lc];
                float* dh = &sAh[row * SSTR + lc];
                float* dl = &sAl[row * SSTR + lc];
                float h0 = f2tf(v.x), h1 = f2tf(v.y), h2 = f2tf(v.z), h3 = f2tf(v.w);
                dh[0] = h0; dh[1] = h1; dh[2] = h2; dh[3] = h3;
                dl[0] = f2tf(v.x - h0); dl[1] = f2tf(v.y - h1);
                dl[2] = f2tf(v.z - h2); dl[3] = f2tf(v.w - h3);
            }
            // load B tile: BN x BK (row remapped for LSTM mode), split hi/lo
            {
                int row = lr;
                float4 v = make_float4(0.f, 0.f, 0.f, 0.f);
                if (p.mode == 2) {
                    int grow = (row >> 4) * p.H + bx * 16 + (row & 15);
                    v = *(const float4*)&B[(size_t)grow * K + k0 + lc];
                } else {
                    int grow = bx * BN + row;
                    if (grow < p.N)
                        v = *(const float4*)&B[(size_t)grow * K + k0 + lc];
                }
                float* dh = &sBh[row * SSTR + lc];
                float* dl = &sBl[row * SSTR + lc];
                float h0 = f2tf(v.x), h1 = f2tf(v.y), h2 = f2tf(v.z), h3 = f2tf(v.w);
                dh[0] = h0; dh[1] = h1; dh[2] = h2; dh[3] = h3;
                dl[0] = f2tf(v.x - h0); dl[1] = f2tf(v.y - h1);
                dl[2] = f2tf(v.z - h2); dl[3] = f2tf(v.w - h3);
            }
            __syncthreads();
#pragma unroll
            for (int kk = 0; kk < BK; kk += 8) {
                unsigned ah[2][4], al[2][4], bh[4][2], bl[4][2];
#pragma unroll
                for (int mt = 0; mt < 2; ++mt) {
                    int r = wm * 32 + mt * 16 + (lane >> 2);
                    int c = kk + (lane & 3);
                    ah[mt][0] = __float_as_uint(sAh[r * SSTR + c]);
                    ah[mt][1] = __float_as_uint(sAh[(r + 8) * SSTR + c]);
                    ah[mt][2] = __float_as_uint(sAh[r * SSTR + c + 4]);
                    ah[mt][3] = __float_as_uint(sAh[(r + 8) * SSTR + c + 4]);
                    al[mt][0] = __float_as_uint(sAl[r * SSTR + c]);
                    al[mt][1] = __float_as_uint(sAl[(r + 8) * SSTR + c]);
                    al[mt][2] = __float_as_uint(sAl[r * SSTR + c + 4]);
                    al[mt][3] = __float_as_uint(sAl[(r + 8) * SSTR + c + 4]);
                }
#pragma unroll
                for (int nt = 0; nt < 4; ++nt) {
                    int n = wn * 32 + nt * 8 + (lane >> 2);
                    int c = kk + (lane & 3);
                    bh[nt][0] = __float_as_uint(sBh[n * SSTR + c]);
                    bh[nt][1] = __float_as_uint(sBh[n * SSTR + c + 4]);
                    bl[nt][0] = __float_as_uint(sBl[n * SSTR + c]);
                    bl[nt][1] = __float_as_uint(sBl[n * SSTR + c + 4]);
                }
#define MMA(ACC, AF, BF)                                                         \
    asm volatile(                                                                \
        "mma.sync.aligned.m16n8k8.row.col.f32.tf32.tf32.f32 "                    \
        "{%0,%1,%2,%3}, {%4,%5,%6,%7}, {%8,%9}, {%0,%1,%2,%3};"                  \
        : "+f"(ACC[0]), "+f"(ACC[1]), "+f"(ACC[2]), "+f"(ACC[3])                 \
        : "r"(AF[0]), "r"(AF[1]), "r"(AF[2]), "r"(AF[3]), "r"(BF[0]), "r"(BF[1]))
#pragma unroll
                for (int mt = 0; mt < 2; ++mt)
#pragma unroll
                    for (int nt = 0; nt < 4; ++nt) {
                        MMA(acc[mt][nt], ah[mt], bl[nt]);
                        MMA(acc[mt][nt], al[mt], bh[nt]);
                        MMA(acc[mt][nt], ah[mt], bh[nt]);
                    }
#undef MMA
            }
        }
    }

    if (p.mode != 2) {
        // plain / tanh epilogue
#pragma unroll
        for (int mt = 0; mt < 2; ++mt)
#pragma unroll
            for (int nt = 0; nt < 4; ++nt) {
                int row0 = m0 + wm * 32 + mt * 16 + (lane >> 2);
                int cl = wn * 32 + nt * 8 + (lane & 3) * 2;
#pragma unroll
                for (int rg = 0; rg < 4; ++rg) {
                    int row = row0 + ((rg >= 2) ? 8 : 0);
                    int n = bx * BN + cl + (rg & 1);
                    if (n < p.N) {
                        float v = acc[mt][nt][rg];
                        if (p.bias1) v += p.bias1[n];
                        if (p.bias2) v += p.bias2[n];
                        if (p.mode == 1) v = tanhf(v);
                        p.C[(size_t)row * p.ldc + n] = v;
                        if (p.C2) p.C2[(size_t)row * p.ldc2 + n] = v;
                    }
                }
            }
    } else {
        // LSTM fused epilogue: stage gates in smem, then pointwise
        __syncthreads();
#pragma unroll
        for (int mt = 0; mt < 2; ++mt)
#pragma unroll
            for (int nt = 0; nt < 4; ++nt) {
#pragma unroll
                for (int rg = 0; rg < 4; ++rg) {
                    int ml = wm * 32 + mt * 16 + (lane >> 2) + ((rg >= 2) ? 8 : 0);
                    int l = wn * 32 + nt * 8 + (lane & 3) * 2 + (rg & 1);
                    int gate = l >> 4, hl = l & 15;
                    smem[(gate * BM + ml) * 16 + hl] = acc[mt][nt][rg];
                }
            }
        __syncthreads();
        for (int i = tid; i < BM * 16; i += 256) {
            int ml = i >> 4, hl = i & 15;
            int b = m0 + ml;
            int hg = bx * 16 + hl;
            float gi = smem[(0 * BM + ml) * 16 + hl] + p.bias1[0 * p.H + hg] + p.bias2[0 * p.H + hg];
            float gf = smem[(1 * BM + ml) * 16 + hl] + p.bias1[1 * p.H + hg] + p.bias2[1 * p.H + hg];
            float gg = smem[(2 * BM + ml) * 16 + hl] + p.bias1[2 * p.H + hg] + p.bias2[2 * p.H + hg];
            float go = smem[(3 * BM + ml) * 16 + hl] + p.bias1[3 * p.H + hg] + p.bias2[3 * p.H + hg];
            size_t ci = (size_t)b * p.H + hg;
            float c = sigm(gf) * p.c_st[ci] + sigm(gi) * tanhf(gg);
            p.c_st[ci] = c;
            p.h_out[ci] = sigm(go) * tanhf(c);
        }
    }
}

// ---------------- host: launch sequence ----------------
extern "C" void kernel_launch(void* const* d_in, const int* in_sizes, int n_in,
                              void* d_out, int out_size) {
    const float* ctx    = (const float*)d_in[0];
    const float* goal0  = (const float*)d_in[1];
    const float* w0     = (const float*)d_in[2];
    const float* bg_W   = (const float*)d_in[3];
    const float* bg_b   = (const float*)d_in[4];
    const float* bw_W   = (const float*)d_in[5];
    const float* bw_b   = (const float*)d_in[6];
    const float* fcg_W  = (const float*)d_in[7];
    const float* fcg_b  = (const float*)d_in[8];
    const float* fcw_W  = (const float*)d_in[9];
    const float* fcw_b  = (const float*)d_in[10];
    const float* lg_Wih = (const float*)d_in[11];
    const float* lg_Whh = (const float*)d_in[12];
    const float* lg_bih = (const float*)d_in[13];
    const float* lg_bhh = (const float*)d_in[14];
    const float* lw_Wih = (const float*)d_in[15];
    const float* lw_Whh = (const float*)d_in[16];
    const float* lw_bih = (const float*)d_in[17];
    const float* lw_bhh = (const float*)d_in[18];
    const float* og_W   = (const float*)d_in[19];
    const float* og_b   = (const float*)d_in[20];
    const float* ow_W   = (const float*)d_in[21];
    const float* ow_b   = (const float*)d_in[22];
    float* out = (float*)d_out;

    void* sym = nullptr;
    cudaGetSymbolAddress(&sym, g_buf);
    float* Gb = (float*)sym;
    float* P_TMPW = Gb + OFF_TMPW;
    float* P_BWT  = Gb + OFF_BWT;
    float* P_XPRE = Gb + OFF_XPRE;
    float* P_YPRE = Gb + OFF_YPRE;
    float* P_X    = Gb + OFF_X;
    float* P_Y    = Gb + OFF_Y;
    float* P_PG   = Gb + OFF_PG;
    float* P_PW   = Gb + OFF_PW;
    float* GH0[2] = {Gb + OFF_GH0A, Gb + OFF_GH0B};
    float* GH1[2] = {Gb + OFF_GH1A, Gb + OFF_GH1B};
    float* WH0[2] = {Gb + OFF_WH0A, Gb + OFF_WH0B};
    float* WH1[2] = {Gb + OFF_WH1A, Gb + OFF_WH1B};
    float* P_GC0  = Gb + OFF_GC0;
    float* P_GC1  = Gb + OFF_GC1;
    float* P_WC0  = Gb + OFF_WC0;
    float* P_WC1  = Gb + OFF_WC1;

    Prob NUL = {};

    // ---- precompute (loop-invariant) + init ----
    k_transpose_ctx<<<512, 256>>>(ctx);
    k_transb<<<dim3(10, 16, 512), dim3(32, 8)>>>(bw_W);
    k_tmpg<<<256, 256>>>(bg_W);
    k_init<<<(int)((SZ_ZERO + CB * DOF + CB * WSZ + 255) / 256), 256>>>(goal0, w0, out);

    {   // tmp_w = ctx @ bwT^T  : M=256, N=156672, K=512
        Prob pc = NUL;
        pc.A1 = ctx; pc.B1 = P_BWT; pc.K1 = CTXD;
        pc.C = P_TMPW; pc.ldc = NW;
        pc.M = CB; pc.N = NW; pc.mode = 0;
        k_mma<<<dim3(NW / BN, CB / BM, 1), 256>>>(pc, pc);
    }

    for (int t = 1; t <= NSTEP; ++t) {
        int ip = (t - 1) & 1, op = t & 1;

        // 1) bilinear
        k_bilinear<<<dim3(CB, 9), 256>>>(bg_b, bw_b);

        // 2) fc + tanh (dual)
        {
            Prob a = NUL, b = NUL;
            a.A1 = P_XPRE; a.B1 = fcg_W; a.K1 = PGD; a.bias1 = fcg_b;
            a.C = P_X; a.ldc = PGD; a.M = CB; a.N = PGD; a.mode = 1;
            b.A1 = P_YPRE; b.B1 = fcw_W; b.K1 = PWD; b.bias1 = fcw_b;
            b.C = P_Y; b.ldc = PWD; b.M = CB; b.N = PWD; b.mode = 1;
            k_mma<<<dim3(8, CB / BM, 2), 256>>>(a, b);
        }

        // 3) LSTM layer 0 (fused gates + pointwise)
        {
            Prob a = NUL, b = NUL;
            a.A1 = P_X;       a.B1 = lg_Wih; a.K1 = PGD;
            a.A2 = GH0[ip];   a.B2 = lg_Whh; a.K2 = HGD;
            a.bias1 = lg_bih; a.bias2 = lg_bhh;
            a.M = CB; a.mode = 2; a.H = HGD; a.c_st = P_GC0; a.h_out = GH0[op];
            b.A1 = P_Y;       b.B1 = lw_Wih; b.K1 = PWD;
            b.A2 = WH0[ip];   b.B2 = lw_Whh; b.K2 = HWD;
            b.bias1 = lw_bih; b.bias2 = lw_bhh;
            b.M = CB; b.mode = 2; b.H = HWD; b.c_st = P_WC0; b.h_out = WH0[op];
            k_mma<<<dim3(HWD / 16, CB / BM, 2), 256>>>(a, b);
        }

        // 4) LSTM layer 1
        {
            Prob a = NUL, b = NUL;
            a.A1 = GH0[op];   a.B1 = lg_Wih + (size_t)4 * HGD * HGD; a.K1 = HGD;
            a.A2 = GH1[ip];   a.B2 = lg_Whh + (size_t)4 * HGD * HGD; a.K2 = HGD;
            a.bias1 = lg_bih + 4 * HGD; a.bias2 = lg_bhh + 4 * HGD;
            a.M = CB; a.mode = 2; a.H = HGD; a.c_st = P_GC1; a.h_out = GH1[op];
            b.A1 = WH0[op];   b.B1 = lw_Wih + (size_t)4 * HWD * HWD; b.K1 = HWD;
            b.A2 = WH1[ip];   b.B2 = lw_Whh + (size_t)4 * HWD * HWD; b.K2 = HWD;
            b.bias1 = lw_bih + 4 * HWD; b.bias2 = lw_bhh + 4 * HWD;
            b.M = CB; b.mode = 2; b.H = HWD; b.c_st = P_WC1; b.h_out = WH1[op];
            k_mma<<<dim3(HWD / 16, CB / BM, 2), 256>>>(a, b);
        }

        // 5) output projections -> d_out slices (and next-step pg/pw)
        {
            Prob a = NUL, b = NUL;
            a.A1 = GH1[op]; a.B1 = og_W; a.K1 = HGD; a.bias1 = og_b;
            a.C = out + (size_t)t * DOF; a.ldc = 20 * DOF;
            a.C2 = P_PG; a.ldc2 = DOF;
            a.M = CB; a.N = DOF; a.mode = 0;
            b.A1 = WH1[op]; b.B1 = ow_W; b.K1 = HWD; b.bias1 = ow_b;
            b.C = out + (size_t)CB * 20 * DOF + (size_t)t * WSZ; b.ldc = 20 * WSZ;
            b.C2 = P_PW; b.ldc2 = WSZ;
            b.M = CB; b.N = WSZ; b.mode = 0;
            k_mma<<<dim3(5, CB / BM, 2), 256>>>(a, b);
        }
    }
}

// round 12
// speedup vs baseline: 1.7322x; 1.7322x over previous
#include <cuda_runtime.h>
#include <math.h>

// ---------------- problem constants ----------------
constexpr int CB   = 256;   // batch
constexpr int CTXD = 512;
constexpr int DOF  = 6;
constexpr int WSZ  = 300;
constexpr int PGD  = 256;
constexpr int PWD  = 512;
constexpr int HGD  = 256;
constexpr int HWD  = 512;
constexpr int ZD   = 306;   // DOF + WSZ
constexpr int NSTEP = 19;   // max_segments - 1
constexpr int NW   = PWD * ZD;   // 156672 = big-GEMM N

// ---------------- scratch layout (single __device__ array, no allocs) ----------
constexpr size_t OFF_TMPW = 0;                               // [b][j*512+o]
constexpr size_t SZ_TMPW  = (size_t)CB * NW;
constexpr size_t OFF_BWT  = OFF_TMPW + SZ_TMPW;              // [(j*512+o)][i]
constexpr size_t SZ_BWT   = (size_t)NW * CTXD;
constexpr size_t OFF_TMPG = OFF_BWT + SZ_BWT;
constexpr size_t SZ_TMPG  = (size_t)CB * PGD * DOF;
constexpr size_t OFF_CTXT = OFF_TMPG + SZ_TMPG;
constexpr size_t OFF_PG   = OFF_CTXT + (size_t)CTXD * CB;
constexpr size_t OFF_PW   = OFF_PG + (size_t)CB * DOF;
constexpr size_t OFF_XPRE = OFF_PW + (size_t)CB * WSZ;
constexpr size_t OFF_YPRE = OFF_XPRE + (size_t)CB * PGD;
constexpr size_t OFF_X    = OFF_YPRE + (size_t)CB * PWD;
constexpr size_t OFF_Y    = OFF_X + (size_t)CB * PGD;
// zero-init region (states used as step-1 inputs)
constexpr size_t OFF_ZERO = OFF_Y + (size_t)CB * PWD;
constexpr size_t OFF_GH0A = OFF_ZERO;
constexpr size_t OFF_GH1A = OFF_GH0A + (size_t)CB * HGD;
constexpr size_t OFF_WH0A = OFF_GH1A + (size_t)CB * HGD;
constexpr size_t OFF_WH1A = OFF_WH0A + (size_t)CB * HWD;
constexpr size_t OFF_GC0  = OFF_WH1A + (size_t)CB * HWD;
constexpr size_t OFF_GC1  = OFF_GC0 + (size_t)CB * HGD;
constexpr size_t OFF_WC0  = OFF_GC1 + (size_t)CB * HGD;
constexpr size_t OFF_WC1  = OFF_WC0 + (size_t)CB * HWD;
constexpr size_t SZ_ZERO  = OFF_WC1 + (size_t)CB * HWD - OFF_ZERO;
// double-buffer "B" halves (not zeroed)
constexpr size_t OFF_GH0B = OFF_WC1 + (size_t)CB * HWD;
constexpr size_t OFF_GH1B = OFF_GH0B + (size_t)CB * HGD;
constexpr size_t OFF_WH0B = OFF_GH1B + (size_t)CB * HGD;
constexpr size_t OFF_WH1B = OFF_WH0B + (size_t)CB * HWD;
constexpr size_t SZ_TOTAL = OFF_WH1B + (size_t)CB * HWD;

__device__ float g_buf[SZ_TOTAL];

__device__ __forceinline__ float sigm(float x) { return 1.0f / (1.0f + expf(-x)); }

__device__ __forceinline__ float f2tf(float f) {
    unsigned u;
    asm("cvt.rna.tf32.f32 %0, %1;" : "=r"(u) : "f"(f));
    return __uint_as_float(u);
}

// ---------------- setup: transpose ctx + zero states + seed outputs ----------
__global__ void k_setup(const float* __restrict__ ctx,
                        const float* __restrict__ goal0, const float* __restrict__ w0,
                        float* __restrict__ out) {
    int idx = blockIdx.x * 256 + threadIdx.x;
    if (idx < CB * CTXD) {
        int b = idx / CTXD, i = idx % CTXD;
        g_buf[OFF_CTXT + (size_t)i * CB + b] = ctx[idx];
        return;
    }
    idx -= CB * CTXD;
    const int R0 = (int)SZ_ZERO;
    const int R2 = CB * DOF;
    const int R3 = CB * WSZ;
    if (idx < R0) {
        g_buf[OFF_ZERO + idx] = 0.f;
    } else if (idx < R0 + R2) {
        int j = idx - R0;
        float v = goal0[j];
        g_buf[OFF_PG + j] = v;
        out[(size_t)(j / DOF) * 20 * DOF + (j % DOF)] = v;   // goals[:,0,:]
    } else if (idx < R0 + R2 + R3) {
        int j = idx - R0 - R2;
        float v = w0[j];
        g_buf[OFF_PW + j] = v;
        out[(size_t)CB * 20 * DOF + (size_t)(j / WSZ) * 20 * WSZ + (j % WSZ)] = v;
    }
}

// ------ transpose bw_W[o][i][j] -> bwT[(j*512+o)][i]  +  tmp_g compute -------
__global__ void k_transb_tmpg(const float* __restrict__ bwW,
                              const float* __restrict__ bgW) {
    if (blockIdx.z == 512) {
        // tmp_g[b][o][j] = sum_i ctx[b,i] * bg_W[o,i,j]
        int o = blockIdx.y * 16 + blockIdx.x;
        int b = threadIdx.y * 32 + threadIdx.x;
        float acc[DOF];
#pragma unroll
        for (int j = 0; j < DOF; ++j) acc[j] = 0.f;
        const float* ctxT = &g_buf[OFF_CTXT];
        for (int i = 0; i < CTXD; ++i) {
            float c = ctxT[(size_t)i * CB + b];
            const float* w = &bgW[((size_t)o * CTXD + i) * DOF];
#pragma unroll
            for (int j = 0; j < DOF; ++j) acc[j] = fmaf(c, w[j], acc[j]);
        }
        float* outp = &g_buf[OFF_TMPG + ((size_t)b * PGD + o) * DOF];
#pragma unroll
        for (int j = 0; j < DOF; ++j) outp[j] = acc[j];
        return;
    }
    if (blockIdx.x >= 10) return;
    __shared__ float t[32][33];
    int o = blockIdx.z;
    int j0 = blockIdx.x * 32, i0 = blockIdx.y * 32;
    int tx = threadIdx.x, ty = threadIdx.y;   // 32 x 8
#pragma unroll
    for (int r = 0; r < 32; r += 8) {
        int i = i0 + ty + r, j = j0 + tx;
        float v = (j < ZD) ? bwW[((size_t)o * CTXD + i) * ZD + j] : 0.f;
        t[ty + r][tx] = v;
    }
    __syncthreads();
#pragma unroll
    for (int r = 0; r < 32; r += 8) {
        int j = j0 + ty + r, i = i0 + tx;
        if (j < ZD)
            g_buf[OFF_BWT + ((size_t)j * PWD + o) * CTXD + i] = t[tx][ty + r];
    }
}

// ---------------- per-step bilinear (coalesced): ypre + xpre ------------------
// grid (CB, 2), block 512.
// y==0: ypre[b][o] = sum_j tmp_w[b][j*512+o] * z[b][j] + bw_b[o]  (unit-stride)
// y==1: xpre[b][o] = sum_j tmp_g[b][o][j] * pg[b][j] + bg_b[o]
__global__ __launch_bounds__(512) void k_bilinear(const float* __restrict__ bg_b,
                                                  const float* __restrict__ bw_b) {
    int b = blockIdx.x;
    int tid = threadIdx.x;
    if (blockIdx.y == 1) {
        if (tid >= PGD) return;
        int o = tid;
        const float* tg = &g_buf[OFF_TMPG + ((size_t)b * PGD + o) * DOF];
        const float* pg = &g_buf[OFF_PG + (size_t)b * DOF];
        float acc = bg_b[o];
#pragma unroll
        for (int j = 0; j < DOF; ++j) acc = fmaf(tg[j], pg[j], acc);
        g_buf[OFF_XPRE + (size_t)b * PGD + o] = acc;
        return;
    }
    __shared__ float zs[ZD];
    if (tid < ZD)
        zs[tid] = (tid < DOF) ? g_buf[OFF_PG + (size_t)b * DOF + tid]
                              : g_buf[OFF_PW + (size_t)b * WSZ + (tid - DOF)];
    __syncthreads();
    const float* tw = &g_buf[OFF_TMPW + (size_t)b * NW + tid];
    float a0 = 0.f, a1 = 0.f, a2 = 0.f;
    int j = 0;
#pragma unroll 2
    for (; j + 3 <= ZD; j += 3) {
        a0 = fmaf(tw[(size_t)(j + 0) * PWD], zs[j + 0], a0);
        a1 = fmaf(tw[(size_t)(j + 1) * PWD], zs[j + 1], a1);
        a2 = fmaf(tw[(size_t)(j + 2) * PWD], zs[j + 2], a2);
    }
    for (; j < ZD; ++j) a0 = fmaf(tw[(size_t)j * PWD], zs[j], a0);
    g_buf[OFF_YPRE + (size_t)b * PWD + tid] = a0 + a1 + a2 + bw_b[tid];
}

// ================= 3xTF32 mma.sync GEMM-NT (pipelined) =======================
// C[M,N] = ep( A1 @ B1^T + A2 @ B2^T + biases ),  A row-major [M,K], B [N,K]
// hi/lo split: acc += hiA*hiB + hiA*loB + loA*hiB -> ~fp32 accuracy.
// BM=64, BN=64, BK=32; 256 threads = 8 warps (4m x 2n), warp tile 16x32.
// Register-prefetch pipelining over the K loop.

struct Prob {
    const float *A1, *B1; int K1;
    const float *A2, *B2; int K2;     // A2 == nullptr -> single phase
    const float *bias1, *bias2;       // nullable
    float *C;  int ldc;
    float *C2; int ldc2;              // nullable second destination
    int M, N;
    int mode;                         // 0 plain, 1 tanh, 2 lstm
    int H;                            // lstm hidden size
    float *c_st;                      // lstm cell state [b][H] (in/out)
    float *h_out;                     // lstm h output [b][H]
};

#define BM 64
#define BN 64
#define BK 32
#define SSTR 36

__global__ __launch_bounds__(256) void k_mma(Prob p0, Prob p1) {
    Prob p = blockIdx.z ? p1 : p0;
    int bx = blockIdx.x;
    int n_tiles = (p.mode == 2) ? (p.H / 16) : ((p.N + BN - 1) / BN);
    if (bx >= n_tiles) return;
    int m0 = blockIdx.y * BM;

    __shared__ float smem[4 * BM * SSTR];        // 9216 floats = 36KB
    float* sAh = smem;
    float* sAl = smem + BM * SSTR;
    float* sBh = smem + 2 * BM * SSTR;
    float* sBl = smem + 3 * BM * SSTR;

    int tid  = threadIdx.x;
    int lane = tid & 31;
    int warp = tid >> 5;
    int wm = warp & 3;                           // 4 m-warps, 16 rows each
    int wn = warp >> 2;                          // 2 n-warps, 32 cols each

    float acc[4][4];
#pragma unroll
    for (int a = 0; a < 4; ++a)
#pragma unroll
        for (int c = 0; c < 4; ++c) acc[a][c] = 0.f;

    int lr = tid >> 3;                           // 0..31
    int lc = (tid & 7) * 4;                      // 0..28

    int n1 = p.K1 / BK;
    int n2 = p.A2 ? (p.K2 / BK) : 0;
    int nIter = n1 + n2;

    float4 ca0, ca1, cb0, cb1, na0, na1, nb0, nb1;

    auto glb = [&](int it, float4& a0, float4& a1, float4& b0, float4& b1) {
        const float *A, *B; int K, kof;
        if (it < n1) { A = p.A1; B = p.B1; K = p.K1; kof = it * BK; }
        else         { A = p.A2; B = p.B2; K = p.K2; kof = (it - n1) * BK; }
        a0 = *(const float4*)&A[(size_t)(m0 + lr) * K + kof + lc];
        a1 = *(const float4*)&A[(size_t)(m0 + lr + 32) * K + kof + lc];
        int g0, g1;
        if (p.mode == 2) {
            g0 = (lr >> 4) * p.H + bx * 16 + (lr & 15);
            g1 = ((lr + 32) >> 4) * p.H + bx * 16 + (lr & 15);
        } else {
            g0 = bx * BN + lr; g1 = bx * BN + lr + 32;
        }
        b0 = make_float4(0.f, 0.f, 0.f, 0.f); b1 = b0;
        if (p.mode == 2 || g0 < p.N) b0 = *(const float4*)&B[(size_t)g0 * K + kof + lc];
        if (p.mode == 2 || g1 < p.N) b1 = *(const float4*)&B[(size_t)g1 * K + kof + lc];
    };

    auto st4 = [&](float* h, float* l, int row, float4 v) {
        float h0 = f2tf(v.x), h1 = f2tf(v.y), h2 = f2tf(v.z), h3 = f2tf(v.w);
        float* dh = &h[row * SSTR + lc];
        float* dl = &l[row * SSTR + lc];
        dh[0] = h0; dh[1] = h1; dh[2] = h2; dh[3] = h3;
        dl[0] = f2tf(v.x - h0); dl[1] = f2tf(v.y - h1);
        dl[2] = f2tf(v.z - h2); dl[3] = f2tf(v.w - h3);
    };

    glb(0, ca0, ca1, cb0, cb1);

#pragma unroll 1
    for (int it = 0; it < nIter; ++it) {
        __syncthreads();
        st4(sAh, sAl, lr,      ca0);
        st4(sAh, sAl, lr + 32, ca1);
        st4(sBh, sBl, lr,      cb0);
        st4(sBh, sBl, lr + 32, cb1);
        __syncthreads();
        if (it + 1 < nIter) glb(it + 1, na0, na1, nb0, nb1);

#define MMA(ACC, AF, BF)                                                         \
    asm volatile(                                                                \
        "mma.sync.aligned.m16n8k8.row.col.f32.tf32.tf32.f32 "                    \
        "{%0,%1,%2,%3}, {%4,%5,%6,%7}, {%8,%9}, {%0,%1,%2,%3};"                  \
        : "+f"(ACC[0]), "+f"(ACC[1]), "+f"(ACC[2]), "+f"(ACC[3])                 \
        : "r"(AF[0]), "r"(AF[1]), "r"(AF[2]), "r"(AF[3]), "r"(BF[0]), "r"(BF[1]))
#pragma unroll
        for (int kk = 0; kk < BK; kk += 8) {
            int c = kk + (lane & 3);
            int r = wm * 16 + (lane >> 2);
            unsigned ah[4], al[4];
            ah[0] = __float_as_uint(sAh[r * SSTR + c]);
            ah[1] = __float_as_uint(sAh[(r + 8) * SSTR + c]);
            ah[2] = __float_as_uint(sAh[r * SSTR + c + 4]);
            ah[3] = __float_as_uint(sAh[(r + 8) * SSTR + c + 4]);
            al[0] = __float_as_uint(sAl[r * SSTR + c]);
            al[1] = __float_as_uint(sAl[(r + 8) * SSTR + c]);
            al[2] = __float_as_uint(sAl[r * SSTR + c + 4]);
            al[3] = __float_as_uint(sAl[(r + 8) * SSTR + c + 4]);
#pragma unroll
            for (int nt = 0; nt < 4; ++nt) {
                int n = wn * 32 + nt * 8 + (lane >> 2);
                unsigned bh[2], bl[2];
                bh[0] = __float_as_uint(sBh[n * SSTR + c]);
                bh[1] = __float_as_uint(sBh[n * SSTR + c + 4]);
                bl[0] = __float_as_uint(sBl[n * SSTR + c]);
                bl[1] = __float_as_uint(sBl[n * SSTR + c + 4]);
                MMA(acc[nt], ah, bl);
                MMA(acc[nt], al, bh);
                MMA(acc[nt], ah, bh);
            }
        }
#undef MMA
        ca0 = na0; ca1 = na1; cb0 = nb0; cb1 = nb1;
    }

    if (p.mode != 2) {
#pragma unroll
        for (int nt = 0; nt < 4; ++nt)
#pragma unroll
            for (int rg = 0; rg < 4; ++rg) {
                int row = m0 + wm * 16 + (lane >> 2) + ((rg >= 2) ? 8 : 0);
                int n = bx * BN + wn * 32 + nt * 8 + (lane & 3) * 2 + (rg & 1);
                if (n < p.N) {
                    float v = acc[nt][rg];
                    if (p.bias1) v += p.bias1[n];
                    if (p.bias2) v += p.bias2[n];
                    if (p.mode == 1) v = tanhf(v);
                    p.C[(size_t)row * p.ldc + n] = v;
                    if (p.C2) p.C2[(size_t)row * p.ldc2 + n] = v;
                }
            }
    } else {
        // stage gates in smem, then fused pointwise
        __syncthreads();
#pragma unroll
        for (int nt = 0; nt < 4; ++nt)
#pragma unroll
            for (int rg = 0; rg < 4; ++rg) {
                int ml = wm * 16 + (lane >> 2) + ((rg >= 2) ? 8 : 0);
                int l = wn * 32 + nt * 8 + (lane & 3) * 2 + (rg & 1);
                smem[((l >> 4) * BM + ml) * 16 + (l & 15)] = acc[nt][rg];
            }
        __syncthreads();
#pragma unroll
        for (int i = tid; i < BM * 16; i += 256) {
            int ml = i >> 4, hl = i & 15;
            int b = m0 + ml;
            int hg = bx * 16 + hl;
            float gi = smem[(0 * BM + ml) * 16 + hl] + p.bias1[0 * p.H + hg] + p.bias2[0 * p.H + hg];
            float gf = smem[(1 * BM + ml) * 16 + hl] + p.bias1[1 * p.H + hg] + p.bias2[1 * p.H + hg];
            float gg = smem[(2 * BM + ml) * 16 + hl] + p.bias1[2 * p.H + hg] + p.bias2[2 * p.H + hg];
            float go = smem[(3 * BM + ml) * 16 + hl] + p.bias1[3 * p.H + hg] + p.bias2[3 * p.H + hg];
            size_t ci = (size_t)b * p.H + hg;
            float c = sigm(gf) * p.c_st[ci] + sigm(gi) * tanhf(gg);
            p.c_st[ci] = c;
            p.h_out[ci] = sigm(go) * tanhf(c);
        }
    }
}

// ---------------- host: launch sequence ----------------
extern "C" void kernel_launch(void* const* d_in, const int* in_sizes, int n_in,
                              void* d_out, int out_size) {
    const float* ctx    = (const float*)d_in[0];
    const float* goal0  = (const float*)d_in[1];
    const float* w0     = (const float*)d_in[2];
    const float* bg_W   = (const float*)d_in[3];
    const float* bg_b   = (const float*)d_in[4];
    const float* bw_W   = (const float*)d_in[5];
    const float* bw_b   = (const float*)d_in[6];
    const float* fcg_W  = (const float*)d_in[7];
    const float* fcg_b  = (const float*)d_in[8];
    const float* fcw_W  = (const float*)d_in[9];
    const float* fcw_b  = (const float*)d_in[10];
    const float* lg_Wih = (const float*)d_in[11];
    const float* lg_Whh = (const float*)d_in[12];
    const float* lg_bih = (const float*)d_in[13];
    const float* lg_bhh = (const float*)d_in[14];
    const float* lw_Wih = (const float*)d_in[15];
    const float* lw_Whh = (const float*)d_in[16];
    const float* lw_bih = (const float*)d_in[17];
    const float* lw_bhh = (const float*)d_in[18];
    const float* og_W   = (const float*)d_in[19];
    const float* og_b   = (const float*)d_in[20];
    const float* ow_W   = (const float*)d_in[21];
    const float* ow_b   = (const float*)d_in[22];
    float* out = (float*)d_out;

    void* sym = nullptr;
    cudaGetSymbolAddress(&sym, g_buf);
    float* Gb = (float*)sym;
    float* P_TMPW = Gb + OFF_TMPW;
    float* P_BWT  = Gb + OFF_BWT;
    float* P_XPRE = Gb + OFF_XPRE;
    float* P_YPRE = Gb + OFF_YPRE;
    float* P_X    = Gb + OFF_X;
    float* P_Y    = Gb + OFF_Y;
    float* P_PG   = Gb + OFF_PG;
    float* P_PW   = Gb + OFF_PW;
    float* GH0[2] = {Gb + OFF_GH0A, Gb + OFF_GH0B};
    float* GH1[2] = {Gb + OFF_GH1A, Gb + OFF_GH1B};
    float* WH0[2] = {Gb + OFF_WH0A, Gb + OFF_WH0B};
    float* WH1[2] = {Gb + OFF_WH1A, Gb + OFF_WH1B};
    float* P_GC0  = Gb + OFF_GC0;
    float* P_GC1  = Gb + OFF_GC1;
    float* P_WC0  = Gb + OFF_WC0;
    float* P_WC1  = Gb + OFF_WC1;

    Prob NUL = {};

    // ---- precompute (loop-invariant) ----
    int setup_blocks = 512 + (int)((SZ_ZERO + CB * DOF + CB * WSZ + 255) / 256);
    k_setup<<<setup_blocks, 256>>>(ctx, goal0, w0, out);
    k_transb_tmpg<<<dim3(16, 16, 513), dim3(32, 8)>>>(bw_W, bg_W);

    {   // tmp_w = ctx @ bwT^T : M=256, N=156672 (n = j*512+o), K=512
        Prob pc = NUL;
        pc.A1 = ctx; pc.B1 = P_BWT; pc.K1 = CTXD;
        pc.C = P_TMPW; pc.ldc = NW;
        pc.M = CB; pc.N = NW; pc.mode = 0;
        k_mma<<<dim3(NW / BN, CB / BM, 1), 256>>>(pc, pc);
    }

    for (int t = 1; t <= NSTEP; ++t) {
        int ip = (t - 1) & 1, op = t & 1;

        // 1) bilinear
        k_bilinear<<<dim3(CB, 2), 512>>>(bg_b, bw_b);

        // 2) fc + tanh (dual)
        {
            Prob a = NUL, b = NUL;
            a.A1 = P_XPRE; a.B1 = fcg_W; a.K1 = PGD; a.bias1 = fcg_b;
            a.C = P_X; a.ldc = PGD; a.M = CB; a.N = PGD; a.mode = 1;
            b.A1 = P_YPRE; b.B1 = fcw_W; b.K1 = PWD; b.bias1 = fcw_b;
            b.C = P_Y; b.ldc = PWD; b.M = CB; b.N = PWD; b.mode = 1;
            k_mma<<<dim3(8, CB / BM, 2), 256>>>(a, b);
        }

        // 3) LSTM layer 0 (fused gates + pointwise)
        {
            Prob a = NUL, b = NUL;
            a.A1 = P_X;       a.B1 = lg_Wih; a.K1 = PGD;
            a.A2 = GH0[ip];   a.B2 = lg_Whh; a.K2 = HGD;
            a.bias1 = lg_bih; a.bias2 = lg_bhh;
            a.M = CB; a.mode = 2; a.H = HGD; a.c_st = P_GC0; a.h_out = GH0[op];
            b.A1 = P_Y;       b.B1 = lw_Wih; b.K1 = PWD;
            b.A2 = WH0[ip];   b.B2 = lw_Whh; b.K2 = HWD;
            b.bias1 = lw_bih; b.bias2 = lw_bhh;
            b.M = CB; b.mode = 2; b.H = HWD; b.c_st = P_WC0; b.h_out = WH0[op];
            k_mma<<<dim3(HWD / 16, CB / BM, 2), 256>>>(a, b);
        }

        // 4) LSTM layer 1
        {
            Prob a = NUL, b = NUL;
            a.A1 = GH0[op];   a.B1 = lg_Wih + (size_t)4 * HGD * HGD; a.K1 = HGD;
            a.A2 = GH1[ip];   a.B2 = lg_Whh + (size_t)4 * HGD * HGD; a.K2 = HGD;
            a.bias1 = lg_bih + 4 * HGD; a.bias2 = lg_bhh + 4 * HGD;
            a.M = CB; a.mode = 2; a.H = HGD; a.c_st = P_GC1; a.h_out = GH1[op];
            b.A1 = WH0[op];   b.B1 = lw_Wih + (size_t)4 * HWD * HWD; b.K1 = HWD;
            b.A2 = WH1[ip];   b.B2 = lw_Whh + (size_t)4 * HWD * HWD; b.K2 = HWD;
            b.bias1 = lw_bih + 4 * HWD; b.bias2 = lw_bhh + 4 * HWD;
            b.M = CB; b.mode = 2; b.H = HWD; b.c_st = P_WC1; b.h_out = WH1[op];
            k_mma<<<dim3(HWD / 16, CB / BM, 2), 256>>>(a, b);
        }

        // 5) output projections -> d_out slices (and next-step pg/pw)
        {
            Prob a = NUL, b = NUL;
            a.A1 = GH1[op]; a.B1 = og_W; a.K1 = HGD; a.bias1 = og_b;
            a.C = out + (size_t)t * DOF; a.ldc = 20 * DOF;
            a.C2 = P_PG; a.ldc2 = DOF;
            a.M = CB; a.N = DOF; a.mode = 0;
            b.A1 = WH1[op]; b.B1 = ow_W; b.K1 = HWD; b.bias1 = ow_b;
            b.C = out + (size_t)CB * 20 * DOF + (size_t)t * WSZ; b.ldc = 20 * WSZ;
            b.C2 = P_PW; b.ldc2 = WSZ;
            b.M = CB; b.N = WSZ; b.mode = 0;
            k_mma<<<dim3(5, CB / BM, 2), 256>>>(a, b);
        }
    }
}

// round 14
// speedup vs baseline: 2.4114x; 1.3921x over previous
#include <cuda_runtime.h>
#include <cuda_fp16.h>
#include <math.h>

// ---------------- problem constants ----------------
constexpr int CB   = 256;   // batch
constexpr int CTXD = 512;
constexpr int DOF  = 6;
constexpr int WSZ  = 300;
constexpr int PGD  = 256;
constexpr int PWD  = 512;
constexpr int HGD  = 256;
constexpr int HWD  = 512;
constexpr int ZD   = 306;   // DOF + WSZ
constexpr int NSTEP = 19;   // max_segments - 1
constexpr int NW   = PWD * ZD;   // 156672 = big-GEMM N

// ---------------- scratch layout (single __device__ array, no allocs) ----------
constexpr size_t OFF_TMPW = 0;                               // [b][j*512+o]
constexpr size_t SZ_TMPW  = (size_t)CB * NW;
constexpr size_t OFF_BWT  = OFF_TMPW + SZ_TMPW;              // [(j*512+o)][i]
constexpr size_t SZ_BWT   = (size_t)NW * CTXD;
constexpr size_t OFF_TMPG = OFF_BWT + SZ_BWT;
constexpr size_t SZ_TMPG  = (size_t)CB * PGD * DOF;
constexpr size_t OFF_CTXT = OFF_TMPG + SZ_TMPG;
constexpr size_t OFF_PG   = OFF_CTXT + (size_t)CTXD * CB;
constexpr size_t OFF_PW   = OFF_PG + (size_t)CB * DOF;
constexpr size_t OFF_XPRE = OFF_PW + (size_t)CB * WSZ;
constexpr size_t OFF_YPRE = OFF_XPRE + (size_t)CB * PGD;
constexpr size_t OFF_X    = OFF_YPRE + (size_t)CB * PWD;
constexpr size_t OFF_Y    = OFF_X + (size_t)CB * PGD;
// zero-init region (states used as step-1 inputs)
constexpr size_t OFF_ZERO = OFF_Y + (size_t)CB * PWD;
constexpr size_t OFF_GH0A = OFF_ZERO;
constexpr size_t OFF_GH1A = OFF_GH0A + (size_t)CB * HGD;
constexpr size_t OFF_WH0A = OFF_GH1A + (size_t)CB * HGD;
constexpr size_t OFF_WH1A = OFF_WH0A + (size_t)CB * HWD;
constexpr size_t OFF_GC0  = OFF_WH1A + (size_t)CB * HWD;
constexpr size_t OFF_GC1  = OFF_GC0 + (size_t)CB * HGD;
constexpr size_t OFF_WC0  = OFF_GC1 + (size_t)CB * HGD;
constexpr size_t OFF_WC1  = OFF_WC0 + (size_t)CB * HWD;
constexpr size_t SZ_ZERO  = OFF_WC1 + (size_t)CB * HWD - OFF_ZERO;
// double-buffer "B" halves (not zeroed)
constexpr size_t OFF_GH0B = OFF_WC1 + (size_t)CB * HWD;
constexpr size_t OFF_GH1B = OFF_GH0B + (size_t)CB * HGD;
constexpr size_t OFF_WH0B = OFF_GH1B + (size_t)CB * HGD;
constexpr size_t OFF_WH1B = OFF_WH0B + (size_t)CB * HWD;
constexpr size_t SZ_TOTAL = OFF_WH1B + (size_t)CB * HWD;

__device__ float g_buf[SZ_TOTAL];

__device__ __forceinline__ float sigm(float x) { return 1.0f / (1.0f + expf(-x)); }

// ---------------- setup: transpose ctx + zero states + seed outputs ----------
__global__ void k_setup(const float* __restrict__ ctx,
                        const float* __restrict__ goal0, const float* __restrict__ w0,
                        float* __restrict__ out) {
    int idx = blockIdx.x * 256 + threadIdx.x;
    if (idx < CB * CTXD) {
        int b = idx / CTXD, i = idx % CTXD;
        g_buf[OFF_CTXT + (size_t)i * CB + b] = ctx[idx];
        return;
    }
    idx -= CB * CTXD;
    const int R0 = (int)SZ_ZERO;
    const int R2 = CB * DOF;
    const int R3 = CB * WSZ;
    if (idx < R0) {
        g_buf[OFF_ZERO + idx] = 0.f;
    } else if (idx < R0 + R2) {
        int j = idx - R0;
        float v = goal0[j];
        g_buf[OFF_PG + j] = v;
        out[(size_t)(j / DOF) * 20 * DOF + (j % DOF)] = v;   // goals[:,0,:]
    } else if (idx < R0 + R2 + R3) {
        int j = idx - R0 - R2;
        float v = w0[j];
        g_buf[OFF_PW + j] = v;
        out[(size_t)CB * 20 * DOF + (size_t)(j / WSZ) * 20 * WSZ + (j % WSZ)] = v;
    }
}

// ------ transpose bw_W[o][i][j] -> bwT[(j*512+o)][i]  +  tmp_g compute -------
__global__ void k_transb_tmpg(const float* __restrict__ bwW,
                              const float* __restrict__ bgW) {
    if (blockIdx.z == 512) {
        // tmp_g[b][o][j] = sum_i ctx[b,i] * bg_W[o,i,j]
        int o = blockIdx.y * 16 + blockIdx.x;
        int b = threadIdx.y * 32 + threadIdx.x;
        float acc[DOF];
#pragma unroll
        for (int j = 0; j < DOF; ++j) acc[j] = 0.f;
        const float* ctxT = &g_buf[OFF_CTXT];
        for (int i = 0; i < CTXD; ++i) {
            float c = ctxT[(size_t)i * CB + b];
            const float* w = &bgW[((size_t)o * CTXD + i) * DOF];
#pragma unroll
            for (int j = 0; j < DOF; ++j) acc[j] = fmaf(c, w[j], acc[j]);
        }
        float* outp = &g_buf[OFF_TMPG + ((size_t)b * PGD + o) * DOF];
#pragma unroll
        for (int j = 0; j < DOF; ++j) outp[j] = acc[j];
        return;
    }
    if (blockIdx.x >= 10) return;
    __shared__ float t[32][33];
    int o = blockIdx.z;
    int j0 = blockIdx.x * 32, i0 = blockIdx.y * 32;
    int tx = threadIdx.x, ty = threadIdx.y;   // 32 x 8
#pragma unroll
    for (int r = 0; r < 32; r += 8) {
        int i = i0 + ty + r, j = j0 + tx;
        float v = (j < ZD) ? bwW[((size_t)o * CTXD + i) * ZD + j] : 0.f;
        t[ty + r][tx] = v;
    }
    __syncthreads();
#pragma unroll
    for (int r = 0; r < 32; r += 8) {
        int j = j0 + ty + r, i = i0 + tx;
        if (j < ZD)
            g_buf[OFF_BWT + ((size_t)j * PWD + o) * CTXD + i] = t[tx][ty + r];
    }
}

// ---------------- per-step bilinear (float4 streaming): ypre + xpre ----------
// grid (CB, 2), block 512.
// y==0: ypre[b][o] = sum_j tmp_w[b][j*512+o]*z[j] + bw_b[o], float4 over o,
//       4 j-phases per thread group, smem reduction.
// y==1: xpre[b][o] = sum_j tmp_g[b][o][j]*pg[b][j] + bg_b[o]
__global__ __launch_bounds__(512) void k_bilinear(const float* __restrict__ bg_b,
                                                  const float* __restrict__ bw_b) {
    int b = blockIdx.x;
    int tid = threadIdx.x;
    if (blockIdx.y == 1) {
        if (tid >= PGD) return;
        int o = tid;
        const float* tg = &g_buf[OFF_TMPG + ((size_t)b * PGD + o) * DOF];
        const float* pg = &g_buf[OFF_PG + (size_t)b * DOF];
        float acc = bg_b[o];
#pragma unroll
        for (int j = 0; j < DOF; ++j) acc = fmaf(tg[j], pg[j], acc);
        g_buf[OFF_XPRE + (size_t)b * PGD + o] = acc;
        return;
    }
    __shared__ float zs[ZD];
    __shared__ float4 red[4][128];
    if (tid < ZD)
        zs[tid] = (tid < DOF) ? g_buf[OFF_PG + (size_t)b * DOF + tid]
                              : g_buf[OFF_PW + (size_t)b * WSZ + (tid - DOF)];
    __syncthreads();
    int og = tid & 127;           // float4 column group (o = og*4 .. og*4+3)
    int jg = tid >> 7;            // 0..3 j-phase
    const float4* tw = (const float4*)&g_buf[OFF_TMPW + (size_t)b * NW];
    float4 acc = make_float4(0.f, 0.f, 0.f, 0.f);
#pragma unroll 4
    for (int j = jg; j < ZD; j += 4) {
        float4 v = tw[j * 128 + og];
        float z = zs[j];
        acc.x = fmaf(v.x, z, acc.x);
        acc.y = fmaf(v.y, z, acc.y);
        acc.z = fmaf(v.z, z, acc.z);
        acc.w = fmaf(v.w, z, acc.w);
    }
    red[jg][og] = acc;
    __syncthreads();
    if (jg == 0) {
        float4 r0 = red[0][og], r1 = red[1][og], r2 = red[2][og], r3 = red[3][og];
        float4 bb = *(const float4*)&bw_b[og * 4];
        float4 s;
        s.x = r0.x + r1.x + r2.x + r3.x + bb.x;
        s.y = r0.y + r1.y + r2.y + r3.y + bb.y;
        s.z = r0.z + r1.z + r2.z + r3.z + bb.z;
        s.w = r0.w + r1.w + r2.w + r3.w + bb.w;
        *(float4*)&g_buf[OFF_YPRE + (size_t)b * PWD + og * 4] = s;
    }
}

// ================= 3xFP16-split mma.sync GEMM-NT (pipelined) =================
// C[M,N] = ep( A1 @ B1^T + A2 @ B2^T + biases ),  A row-major [M,K], B [N,K]
// x = hi_f16 + lo_f16; acc += hiA*hiB + hiA*loB + loA*hiB (fp32 accumulate)
//   -> ~fp32 accuracy (dropped lo*lo term ~2^-24), 2x tf32 MMA throughput.
// BM=64, BN=64, BK=32; 256 threads = 8 warps (4m x 2n), warp tile 16x32.
// Register-prefetch pipelining over the K loop. m16n8k16 fragments.

struct Prob {
    const float *A1, *B1; int K1;
    const float *A2, *B2; int K2;     // A2 == nullptr -> single phase
    const float *bias1, *bias2;       // nullable
    float *C;  int ldc;
    float *C2; int ldc2;              // nullable second destination
    int M, N;
    int mode;                         // 0 plain, 1 tanh, 2 lstm
    int H;                            // lstm hidden size
    float *c_st;                      // lstm cell state [b][H] (in/out)
    float *h_out;                     // lstm h output [b][H]
};

#define BM 64
#define BN 64
#define BK 32
#define SH 40                          // half stride per row

__global__ __launch_bounds__(256) void k_mma(Prob p0, Prob p1) {
    Prob p = blockIdx.z ? p1 : p0;
    int bx = blockIdx.x;
    int n_tiles = (p.mode == 2) ? (p.H / 16) : ((p.N + BN - 1) / BN);
    if (bx >= n_tiles) return;
    int m0 = blockIdx.y * BM;

    __shared__ __align__(16) unsigned char smraw[4 * BM * SH * 2];  // 20480 B
    __half* sAh = (__half*)smraw;
    __half* sAl = sAh + BM * SH;
    __half* sBh = sAl + BM * SH;
    __half* sBl = sBh + BM * SH;
    float* gates = (float*)smraw;                                   // reuse, 16KB

    int tid  = threadIdx.x;
    int lane = tid & 31;
    int warp = tid >> 5;
    int wm = warp & 3;                           // 4 m-warps, 16 rows each
    int wn = warp >> 2;                          // 2 n-warps, 32 cols each

    float acc[4][4];
#pragma unroll
    for (int a = 0; a < 4; ++a)
#pragma unroll
        for (int c = 0; c < 4; ++c) acc[a][c] = 0.f;

    int lr = tid >> 3;                           // 0..31
    int lc = (tid & 7) * 4;                      // 0..28 (half col offset)

    int n1 = p.K1 / BK;
    int n2 = p.A2 ? (p.K2 / BK) : 0;
    int nIter = n1 + n2;

    float4 ca0, ca1, cb0, cb1, na0, na1, nb0, nb1;

    auto glb = [&](int it, float4& a0, float4& a1, float4& b0, float4& b1) {
        const float *A, *B; int K, kof;
        if (it < n1) { A = p.A1; B = p.B1; K = p.K1; kof = it * BK; }
        else         { A = p.A2; B = p.B2; K = p.K2; kof = (it - n1) * BK; }
        a0 = *(const float4*)&A[(size_t)(m0 + lr) * K + kof + lc];
        a1 = *(const float4*)&A[(size_t)(m0 + lr + 32) * K + kof + lc];
        int g0, g1;
        if (p.mode == 2) {
            g0 = (lr >> 4) * p.H + bx * 16 + (lr & 15);
            g1 = ((lr + 32) >> 4) * p.H + bx * 16 + (lr & 15);
        } else {
            g0 = bx * BN + lr; g1 = bx * BN + lr + 32;
        }
        b0 = make_float4(0.f, 0.f, 0.f, 0.f); b1 = b0;
        if (p.mode == 2 || g0 < p.N) b0 = *(const float4*)&B[(size_t)g0 * K + kof + lc];
        if (p.mode == 2 || g1 < p.N) b1 = *(const float4*)&B[(size_t)g1 * K + kof + lc];
    };

    auto st4 = [&](__half* h, __half* l, int row, float4 v) {
        __half h0 = __float2half_rn(v.x), h1 = __float2half_rn(v.y);
        __half h2 = __float2half_rn(v.z), h3 = __float2half_rn(v.w);
        __half l0 = __float2half_rn(v.x - __half2float(h0));
        __half l1 = __float2half_rn(v.y - __half2float(h1));
        __half l2 = __float2half_rn(v.z - __half2float(h2));
        __half l3 = __float2half_rn(v.w - __half2float(h3));
        *(__half2*)&h[row * SH + lc]     = __halves2half2(h0, h1);
        *(__half2*)&h[row * SH + lc + 2] = __halves2half2(h2, h3);
        *(__half2*)&l[row * SH + lc]     = __halves2half2(l0, l1);
        *(__half2*)&l[row * SH + lc + 2] = __halves2half2(l2, l3);
    };

    glb(0, ca0, ca1, cb0, cb1);

#pragma unroll 1
    for (int it = 0; it < nIter; ++it) {
        __syncthreads();
        st4(sAh, sAl, lr,      ca0);
        st4(sAh, sAl, lr + 32, ca1);
        st4(sBh, sBl, lr,      cb0);
        st4(sBh, sBl, lr + 32, cb1);
        __syncthreads();
        if (it + 1 < nIter) glb(it + 1, na0, na1, nb0, nb1);

#define MMA16(ACC, AF, BF)                                                       \
    asm volatile(                                                                \
        "mma.sync.aligned.m16n8k16.row.col.f32.f16.f16.f32 "                     \
        "{%0,%1,%2,%3}, {%4,%5,%6,%7}, {%8,%9}, {%0,%1,%2,%3};"                  \
        : "+f"(ACC[0]), "+f"(ACC[1]), "+f"(ACC[2]), "+f"(ACC[3])                 \
        : "r"(AF[0]), "r"(AF[1]), "r"(AF[2]), "r"(AF[3]), "r"(BF[0]), "r"(BF[1]))
#pragma unroll
        for (int kk = 0; kk < BK; kk += 16) {
            int c = kk + (lane & 3) * 2;
            int r = wm * 16 + (lane >> 2);
            unsigned ah[4], al[4];
            ah[0] = *(const unsigned*)&sAh[r * SH + c];
            ah[1] = *(const unsigned*)&sAh[(r + 8) * SH + c];
            ah[2] = *(const unsigned*)&sAh[r * SH + c + 8];
            ah[3] = *(const unsigned*)&sAh[(r + 8) * SH + c + 8];
            al[0] = *(const unsigned*)&sAl[r * SH + c];
            al[1] = *(const unsigned*)&sAl[(r + 8) * SH + c];
            al[2] = *(const unsigned*)&sAl[r * SH + c + 8];
            al[3] = *(const unsigned*)&sAl[(r + 8) * SH + c + 8];
#pragma unroll
            for (int nt = 0; nt < 4; ++nt) {
                int n = wn * 32 + nt * 8 + (lane >> 2);
                unsigned bh[2], bl[2];
                bh[0] = *(const unsigned*)&sBh[n * SH + c];
                bh[1] = *(const unsigned*)&sBh[n * SH + c + 8];
                bl[0] = *(const unsigned*)&sBl[n * SH + c];
                bl[1] = *(const unsigned*)&sBl[n * SH + c + 8];
                MMA16(acc[nt], ah, bl);
                MMA16(acc[nt], al, bh);
                MMA16(acc[nt], ah, bh);
            }
        }
#undef MMA16
        ca0 = na0; ca1 = na1; cb0 = nb0; cb1 = nb1;
    }

    if (p.mode != 2) {
#pragma unroll
        for (int nt = 0; nt < 4; ++nt)
#pragma unroll
            for (int rg = 0; rg < 4; ++rg) {
                int row = m0 + wm * 16 + (lane >> 2) + ((rg >= 2) ? 8 : 0);
                int n = bx * BN + wn * 32 + nt * 8 + (lane & 3) * 2 + (rg & 1);
                if (n < p.N) {
                    float v = acc[nt][rg];
                    if (p.bias1) v += p.bias1[n];
                    if (p.bias2) v += p.bias2[n];
                    if (p.mode == 1) v = tanhf(v);
                    p.C[(size_t)row * p.ldc + n] = v;
                    if (p.C2) p.C2[(size_t)row * p.ldc2 + n] = v;
                }
            }
    } else {
        // stage gates in smem, then fused pointwise
        __syncthreads();
#pragma unroll
        for (int nt = 0; nt < 4; ++nt)
#pragma unroll
            for (int rg = 0; rg < 4; ++rg) {
                int ml = wm * 16 + (lane >> 2) + ((rg >= 2) ? 8 : 0);
                int l = wn * 32 + nt * 8 + (lane & 3) * 2 + (rg & 1);
                gates[((l >> 4) * BM + ml) * 16 + (l & 15)] = acc[nt][rg];
            }
        __syncthreads();
#pragma unroll
        for (int i = tid; i < BM * 16; i += 256) {
            int ml = i >> 4, hl = i & 15;
            int b = m0 + ml;
            int hg = bx * 16 + hl;
            float gi = gates[(0 * BM + ml) * 16 + hl] + p.bias1[0 * p.H + hg] + p.bias2[0 * p.H + hg];
            float gf = gates[(1 * BM + ml) * 16 + hl] + p.bias1[1 * p.H + hg] + p.bias2[1 * p.H + hg];
            float gg = gates[(2 * BM + ml) * 16 + hl] + p.bias1[2 * p.H + hg] + p.bias2[2 * p.H + hg];
            float go = gates[(3 * BM + ml) * 16 + hl] + p.bias1[3 * p.H + hg] + p.bias2[3 * p.H + hg];
            size_t ci = (size_t)b * p.H + hg;
            float c = sigm(gf) * p.c_st[ci] + sigm(gi) * tanhf(gg);
            p.c_st[ci] = c;
            p.h_out[ci] = sigm(go) * tanhf(c);
        }
    }
}

// ---------------- host: launch sequence ----------------
extern "C" void kernel_launch(void* const* d_in, const int* in_sizes, int n_in,
                              void* d_out, int out_size) {
    const float* ctx    = (const float*)d_in[0];
    const float* goal0  = (const float*)d_in[1];
    const float* w0     = (const float*)d_in[2];
    const float* bg_W   = (const float*)d_in[3];
    const float* bg_b   = (const float*)d_in[4];
    const float* bw_W   = (const float*)d_in[5];
    const float* bw_b   = (const float*)d_in[6];
    const float* fcg_W  = (const float*)d_in[7];
    const float* fcg_b  = (const float*)d_in[8];
    const float* fcw_W  = (const float*)d_in[9];
    const float* fcw_b  = (const float*)d_in[10];
    const float* lg_Wih = (const float*)d_in[11];
    const float* lg_Whh = (const float*)d_in[12];
    const float* lg_bih = (const float*)d_in[13];
    const float* lg_bhh = (const float*)d_in[14];
    const float* lw_Wih = (const float*)d_in[15];
    const float* lw_Whh = (const float*)d_in[16];
    const float* lw_bih = (const float*)d_in[17];
    const float* lw_bhh = (const float*)d_in[18];
    const float* og_W   = (const float*)d_in[19];
    const float* og_b   = (const float*)d_in[20];
    const float* ow_W   = (const float*)d_in[21];
    const float* ow_b   = (const float*)d_in[22];
    float* out = (float*)d_out;

    void* sym = nullptr;
    cudaGetSymbolAddress(&sym, g_buf);
    float* Gb = (float*)sym;
    float* P_TMPW = Gb + OFF_TMPW;
    float* P_BWT  = Gb + OFF_BWT;
    float* P_XPRE = Gb + OFF_XPRE;
    float* P_YPRE = Gb + OFF_YPRE;
    float* P_X    = Gb + OFF_X;
    float* P_Y    = Gb + OFF_Y;
    float* P_PG   = Gb + OFF_PG;
    float* P_PW   = Gb + OFF_PW;
    float* GH0[2] = {Gb + OFF_GH0A, Gb + OFF_GH0B};
    float* GH1[2] = {Gb + OFF_GH1A, Gb + OFF_GH1B};
    float* WH0[2] = {Gb + OFF_WH0A, Gb + OFF_WH0B};
    float* WH1[2] = {Gb + OFF_WH1A, Gb + OFF_WH1B};
    float* P_GC0  = Gb + OFF_GC0;
    float* P_GC1  = Gb + OFF_GC1;
    float* P_WC0  = Gb + OFF_WC0;
    float* P_WC1  = Gb + OFF_WC1;

    Prob NUL = {};

    // ---- precompute (loop-invariant) ----
    int setup_blocks = 512 + (int)((SZ_ZERO + CB * DOF + CB * WSZ + 255) / 256);
    k_setup<<<setup_blocks, 256>>>(ctx, goal0, w0, out);
    k_transb_tmpg<<<dim3(16, 16, 513), dim3(32, 8)>>>(bw_W, bg_W);

    {   // tmp_w = ctx @ bwT^T : M=256, N=156672 (n = j*512+o), K=512
        Prob pc = NUL;
        pc.A1 = ctx; pc.B1 = P_BWT; pc.K1 = CTXD;
        pc.C = P_TMPW; pc.ldc = NW;
        pc.M = CB; pc.N = NW; pc.mode = 0;
        k_mma<<<dim3(NW / BN, CB / BM, 1), 256>>>(pc, pc);
    }

    for (int t = 1; t <= NSTEP; ++t) {
        int ip = (t - 1) & 1, op = t & 1;

        // 1) bilinear
        k_bilinear<<<dim3(CB, 2), 512>>>(bg_b, bw_b);

        // 2) fc + tanh (dual)
        {
            Prob a = NUL, b = NUL;
            a.A1 = P_XPRE; a.B1 = fcg_W; a.K1 = PGD; a.bias1 = fcg_b;
            a.C = P_X; a.ldc = PGD; a.M = CB; a.N = PGD; a.mode = 1;
            b.A1 = P_YPRE; b.B1 = fcw_W; b.K1 = PWD; b.bias1 = fcw_b;
            b.C = P_Y; b.ldc = PWD; b.M = CB; b.N = PWD; b.mode = 1;
            k_mma<<<dim3(8, CB / BM, 2), 256>>>(a, b);
        }

        // 3) LSTM layer 0 (fused gates + pointwise)
        {
            Prob a = NUL, b = NUL;
            a.A1 = P_X;       a.B1 = lg_Wih; a.K1 = PGD;
            a.A2 = GH0[ip];   a.B2 = lg_Whh; a.K2 = HGD;
            a.bias1 = lg_bih; a.bias2 = lg_bhh;
            a.M = CB; a.mode = 2; a.H = HGD; a.c_st = P_GC0; a.h_out = GH0[op];
            b.A1 = P_Y;       b.B1 = lw_Wih; b.K1 = PWD;
            b.A2 = WH0[ip];   b.B2 = lw_Whh; b.K2 = HWD;
            b.bias1 = lw_bih; b.bias2 = lw_bhh;
            b.M = CB; b.mode = 2; b.H = HWD; b.c_st = P_WC0; b.h_out = WH0[op];
            k_mma<<<dim3(HWD / 16, CB / BM, 2), 256>>>(a, b);
        }

        // 4) LSTM layer 1
        {
            Prob a = NUL, b = NUL;
            a.A1 = GH0[op];   a.B1 = lg_Wih + (size_t)4 * HGD * HGD; a.K1 = HGD;
            a.A2 = GH1[ip];   a.B2 = lg_Whh + (size_t)4 * HGD * HGD; a.K2 = HGD;
            a.bias1 = lg_bih + 4 * HGD; a.bias2 = lg_bhh + 4 * HGD;
            a.M = CB; a.mode = 2; a.H = HGD; a.c_st = P_GC1; a.h_out = GH1[op];
            b.A1 = WH0[op];   b.B1 = lw_Wih + (size_t)4 * HWD * HWD; b.K1 = HWD;
            b.A2 = WH1[ip];   b.B2 = lw_Whh + (size_t)4 * HWD * HWD; b.K2 = HWD;
            b.bias1 = lw_bih + 4 * HWD; b.bias2 = lw_bhh + 4 * HWD;
            b.M = CB; b.mode = 2; b.H = HWD; b.c_st = P_WC1; b.h_out = WH1[op];
            k_mma<<<dim3(HWD / 16, CB / BM, 2), 256>>>(a, b);
        }

        // 5) output projections -> d_out slices (and next-step pg/pw)
        {
            Prob a = NUL, b = NUL;
            a.A1 = GH1[op]; a.B1 = og_W; a.K1 = HGD; a.bias1 = og_b;
            a.C = out + (size_t)t * DOF; a.ldc = 20 * DOF;
            a.C2 = P_PG; a.ldc2 = DOF;
            a.M = CB; a.N = DOF; a.mode = 0;
            b.A1 = WH1[op]; b.B1 = ow_W; b.K1 = HWD; b.bias1 = ow_b;
            b.C = out + (size_t)CB * 20 * DOF + (size_t)t * WSZ; b.ldc = 20 * WSZ;
            b.C2 = P_PW; b.ldc2 = WSZ;
            b.M = CB; b.N = WSZ; b.mode = 0;
            k_mma<<<dim3(5, CB / BM, 2), 256>>>(a, b);
        }
    }
}